// round 5
// baseline (speedup 1.0000x reference)
#include <cuda_runtime.h>
#include <math.h>

#define BB   16
#define TT   1024
#define NN   128
#define NW   498
#define DM   256
#define IND  384

// ---------------- scratch (static device globals; no allocation) ----------------
__device__ float g_mu  [BB*NW*NN];      // per (b,w,n) window mean
__device__ float g_rstd[BB*NW*NN];      // per (b,w,n) 1/std
__device__ float g_cm  [3*BB*NN*NN];    // central moments d=2,4,8
__device__ float g_rmean[3*BB*NN];
__device__ float g_rinv [3*BB*NN];
__device__ float g_A  [BB*NN*NN];       // averaged ho (diag=1)
__device__ float g_dis[BB*NN];          // rsqrt(rowsum(A)+1)
__device__ float g_X  [BB*NN*IND];      // layernormed features
__device__ float g_P  [BB*NN*DM];
__device__ float g_H  [BB*NN*DM];
__device__ float g_P2 [BB*NN*DM];
__device__ float g_H2 [BB*NN*DM];

__device__ const int c_ti[10] = {0,0,0,0,1,1,1,2,2,3};
__device__ const int c_tj[10] = {0,1,2,3,1,2,3,2,3,3};

#define LD4(p) (*reinterpret_cast<const float4*>(p))

// ---------------- per-(b,w,n) mean / rstd, sliding sums ----------------
__global__ void k_musig(const float* __restrict__ x) {
    int b  = blockIdx.x / 6;
    int ch = blockIdx.x % 6;
    int n  = threadIdx.x;
    int w0 = ch * 83, wend = w0 + 83;           // 6*83 = 498
    const float* xb = x + (size_t)b*TT*NN + n;
    float S = 0.f, Q = 0.f;
    int t0 = 2*w0;
    #pragma unroll
    for (int t = 0; t < 30; ++t) {
        float v = xb[(t0+t)*NN];
        S += v; Q += v*v;
    }
    for (int w = w0; w < wend; ++w) {
        if (w > w0) {
            int tp = 2*(w-1);
            float v0 = xb[tp*NN],      v1 = xb[(tp+1)*NN];
            float a0 = xb[(tp+30)*NN], a1 = xb[(tp+31)*NN];
            S += (a0 + a1) - (v0 + v1);
            Q += (a0*a0 + a1*a1) - (v0*v0 + v1*v1);
        }
        float mu  = S * (1.0f/30.0f);
        float var = (Q - S*S*(1.0f/30.0f)) * (1.0f/29.0f);
        float rs  = rsqrtf(fmaxf(var, 1e-8f));
        int idx = (b*NW + w)*NN + n;
        g_mu[idx]   = mu;
        g_rstd[idx] = rs;
    }
}

// ---------------- main window kernel: sliding Gram, two passes ----------------
__device__ __forceinline__ void gram_full(const float* __restrict__ xb,
                                          int n, int m0, int t0, float4& G) {
    G = make_float4(0.f, 0.f, 0.f, 0.f);
    const float* p = xb + t0*NN;
    #pragma unroll
    for (int t = 0; t < 30; ++t) {
        float  a = p[n];
        float4 v = LD4(p + m0);
        G.x += a*v.x; G.y += a*v.y; G.z += a*v.z; G.w += a*v.w;
        p += NN;
    }
}

__device__ __forceinline__ void gram_slide(const float* __restrict__ xb,
                                           int n, int m0, int w, float4& G) {
    const float* p = xb + (2*w)*NN;
    float a; float4 v;
    a = p[n - 2*NN]; v = LD4(p + m0 - 2*NN);
    G.x -= a*v.x; G.y -= a*v.y; G.z -= a*v.z; G.w -= a*v.w;
    a = p[n - NN];   v = LD4(p + m0 - NN);
    G.x -= a*v.x; G.y -= a*v.y; G.z -= a*v.z; G.w -= a*v.w;
    a = p[n + 28*NN]; v = LD4(p + m0 + 28*NN);
    G.x += a*v.x; G.y += a*v.y; G.z += a*v.z; G.w += a*v.w;
    a = p[n + 29*NN]; v = LD4(p + m0 + 29*NN);
    G.x += a*v.x; G.y += a*v.y; G.z += a*v.z; G.w += a*v.w;
}

__device__ __forceinline__ float4 corr4(const float4& G, float mun, float rn,
                                        const float4& mum, const float4& rm) {
    float s  = (1.0f/29.0f) * rn;
    float t2 = 30.0f * mun;
    float4 c;
    c.x = (G.x - t2*mum.x) * (s*rm.x);
    c.y = (G.y - t2*mum.y) * (s*rm.y);
    c.z = (G.z - t2*mum.z) * (s*rm.z);
    c.w = (G.w - t2*mum.w) * (s*rm.w);
    return c;
}

__global__ void __launch_bounds__(256) k_window(const float* __restrict__ x) {
    int b    = blockIdx.x / 10;
    int tile = blockIdx.x % 10;
    int tin = c_ti[tile], tjn = c_tj[tile];
    int tid = threadIdx.x;
    int n  = tin*32 + (tid >> 3);
    int m0 = tjn*32 + (tid & 7)*4;
    const float* xb = x + (size_t)b*TT*NN;

    float4 G;
    // ---- pass A: mean over windows of corr ----
    gram_full(xb, n, m0, 0, G);
    float4 Cs = make_float4(0.f,0.f,0.f,0.f);
    const float* pmu = g_mu   + b*NW*NN;
    const float* prs = g_rstd + b*NW*NN;
    for (int w = 0; w < NW; ++w) {
        if (w) {
            if ((w & 63) == 0) gram_full(xb, n, m0, 2*w, G);
            else               gram_slide(xb, n, m0, w, G);
        }
        float  mun = pmu[n], rn = prs[n];
        float4 mum = LD4(pmu + m0), rm = LD4(prs + m0);
        float4 c = corr4(G, mun, rn, mum, rm);
        Cs.x += c.x; Cs.y += c.y; Cs.z += c.z; Cs.w += c.w;
        pmu += NN; prs += NN;
    }
    float4 mn;
    mn.x = Cs.x*(1.0f/498.0f); mn.y = Cs.y*(1.0f/498.0f);
    mn.z = Cs.z*(1.0f/498.0f); mn.w = Cs.w*(1.0f/498.0f);

    // ---- pass B: central moments d=2,4,8 ----
    gram_full(xb, n, m0, 0, G);
    float4 p2 = make_float4(0.f,0.f,0.f,0.f);
    float4 p4 = make_float4(0.f,0.f,0.f,0.f);
    float4 p8 = make_float4(0.f,0.f,0.f,0.f);
    pmu = g_mu   + b*NW*NN;
    prs = g_rstd + b*NW*NN;
    for (int w = 0; w < NW; ++w) {
        if (w) {
            if ((w & 63) == 0) gram_full(xb, n, m0, 2*w, G);
            else               gram_slide(xb, n, m0, w, G);
        }
        float  mun = pmu[n], rn = prs[n];
        float4 mum = LD4(pmu + m0), rm = LD4(prs + m0);
        float4 c = corr4(G, mun, rn, mum, rm);
        float dx = c.x - mn.x, dy = c.y - mn.y, dz = c.z - mn.z, dw = c.w - mn.w;
        float d2x = dx*dx, d2y = dy*dy, d2z = dz*dz, d2w = dw*dw;
        p2.x += d2x; p2.y += d2y; p2.z += d2z; p2.w += d2w;
        float d4x = d2x*d2x, d4y = d2y*d2y, d4z = d2z*d2z, d4w = d2w*d2w;
        p4.x += d4x; p4.y += d4y; p4.z += d4z; p4.w += d4w;
        p8.x += d4x*d4x; p8.y += d4y*d4y; p8.z += d4z*d4z; p8.w += d4w*d4w;
        pmu += NN; prs += NN;
    }

    const float inv = 1.0f/498.0f;
    float a2[4] = {p2.x,p2.y,p2.z,p2.w};
    float a4[4] = {p4.x,p4.y,p4.z,p4.w};
    float a8[4] = {p8.x,p8.y,p8.z,p8.w};
    const int D = BB*NN*NN;
    #pragma unroll
    for (int i = 0; i < 4; ++i) {
        int m = m0 + i;
        float v2 = a2[i]*inv, v4 = a4[i]*inv, v8 = a8[i]*inv;
        if (n == m) { v2 = 0.f; v4 = 0.f; v8 = 0.f; }   // diag corr==1 exactly
        int idx = (b*NN + n)*NN + m;
        g_cm[idx] = v2; g_cm[D + idx] = v4; g_cm[2*D + idx] = v8;
        if (tin != tjn) {
            int tdx = (b*NN + m)*NN + n;
            g_cm[tdx] = v2; g_cm[D + tdx] = v4; g_cm[2*D + tdx] = v8;
        }
    }
}

// ---------------- row stats of cm (for rowwise_corr) ----------------
__global__ void k_rowstats() {
    __shared__ float sm[NN];
    int row = blockIdx.x;          // (d*BB+b)*NN + n
    int t = threadIdx.x;
    float v = g_cm[row*NN + t];
    sm[t] = v; __syncthreads();
    for (int s = 64; s > 0; s >>= 1) { if (t < s) sm[t] += sm[t+s]; __syncthreads(); }
    float mean = sm[0] * (1.0f/128.0f);
    __syncthreads();
    float c = v - mean;
    sm[t] = c*c; __syncthreads();
    for (int s = 64; s > 0; s >>= 1) { if (t < s) sm[t] += sm[t+s]; __syncthreads(); }
    if (t == 0) {
        g_rmean[row] = mean;
        g_rinv[row]  = rsqrtf(fmaxf(sm[0], 1e-8f));
    }
}

// ---------------- ho = rowwise corr of each cm_d, averaged -> A, dis ----------------
__global__ void k_ho() {
    __shared__ float rowc[3][4][NN];
    __shared__ float rin[3][4];
    __shared__ float red[NN];
    int b  = blockIdx.x / 32;
    int n0 = (blockIdx.x % 32) * 4;
    int t  = threadIdx.x;                     // = m
    #pragma unroll
    for (int d = 0; d < 3; ++d)
        #pragma unroll
        for (int r = 0; r < 4; ++r) {
            int row = (d*BB + b)*NN + n0 + r;
            rowc[d][r][t] = g_cm[row*NN + t] - g_rmean[row];
        }
    if (t < 12) { int d = t/4, r = t%4; rin[d][r] = g_rinv[(d*BB+b)*NN + n0 + r]; }
    __syncthreads();

    int m = t;
    float rm_m[3], ri_m[3];
    #pragma unroll
    for (int d = 0; d < 3; ++d) {
        rm_m[d] = g_rmean[(d*BB+b)*NN + m];
        ri_m[d] = g_rinv [(d*BB+b)*NN + m];
    }
    float acc[3][4] = {{0}};
    for (int f = 0; f < NN; ++f) {
        #pragma unroll
        for (int d = 0; d < 3; ++d) {
            float col = g_cm[((d*BB+b)*NN + f)*NN + m] - rm_m[d];  // cm symmetric
            acc[d][0] += rowc[d][0][f]*col;
            acc[d][1] += rowc[d][1][f]*col;
            acc[d][2] += rowc[d][2][f]*col;
            acc[d][3] += rowc[d][3][f]*col;
        }
    }
    float Av[4];
    #pragma unroll
    for (int r = 0; r < 4; ++r) {
        float s = 0.f;
        #pragma unroll
        for (int d = 0; d < 3; ++d) {
            float corr = acc[d][r] * rin[d][r] * ri_m[d];
            if (n0 + r == m) corr = 1.0f;
            s += corr;
        }
        Av[r] = s * (1.0f/3.0f);
        g_A[(b*NN + n0 + r)*NN + m] = Av[r];
    }
    for (int r = 0; r < 4; ++r) {
        red[t] = Av[r]; __syncthreads();
        for (int s = 64; s > 0; s >>= 1) { if (t < s) red[t] += red[t+s]; __syncthreads(); }
        if (t == 0) g_dis[b*NN + n0 + r] = rsqrtf(fmaxf(red[0] + 1.0f, 1e-8f));
        __syncthreads();
    }
}

// ---------------- X = layernorm(concat(cm2,cm4,cm8)) ----------------
__global__ void k_ln(const float* __restrict__ gam, const float* __restrict__ bet) {
    __shared__ float red[NN];
    int b = blockIdx.x / NN, n = blockIdx.x % NN, t = threadIdx.x;
    float v[3];
    #pragma unroll
    for (int d = 0; d < 3; ++d) v[d] = g_cm[((d*BB+b)*NN + n)*NN + t];
    red[t] = v[0] + v[1] + v[2]; __syncthreads();
    for (int s = 64; s > 0; s >>= 1) { if (t < s) red[t] += red[t+s]; __syncthreads(); }
    float mean = red[0] * (1.0f/384.0f);
    __syncthreads();
    float q = 0.f;
    #pragma unroll
    for (int d = 0; d < 3; ++d) { float c = v[d]-mean; q += c*c; }
    red[t] = q; __syncthreads();
    for (int s = 64; s > 0; s >>= 1) { if (t < s) red[t] += red[t+s]; __syncthreads(); }
    float rs = rsqrtf(red[0]*(1.0f/384.0f) + 1e-5f);
    #pragma unroll
    for (int d = 0; d < 3; ++d) {
        int f = d*NN + t;
        g_X[(b*NN + n)*IND + f] = (v[d]-mean)*rs*gam[f] + bet[f];
    }
}

// ---------------- generic small SGEMM: C = In@W + bias ----------------
__device__ __forceinline__ void gemm_body(const float* __restrict__ In,
                                          const float* __restrict__ W,
                                          const float* __restrict__ bias,
                                          float* __restrict__ C, int K) {
    __shared__ float As[32][33];
    __shared__ float Bs[32][33];
    int tx = threadIdx.x, ty = threadIdx.y;
    int tid = ty*16 + tx;
    int row0 = blockIdx.y*32, col0 = blockIdx.x*32;
    float a00=0.f, a01=0.f, a10=0.f, a11=0.f;
    for (int k0 = 0; k0 < K; k0 += 32) {
        #pragma unroll
        for (int l = 0; l < 4; ++l) {
            int e = tid + l*256; int i = e>>5, j = e&31;
            As[i][j] = In[(row0+i)*K + k0 + j];
            Bs[i][j] = W [(k0+i)*DM + col0 + j];
        }
        __syncthreads();
        #pragma unroll
        for (int kk = 0; kk < 32; ++kk) {
            float x0 = As[ty*2][kk],   x1 = As[ty*2+1][kk];
            float w0 = Bs[kk][tx*2],   w1 = Bs[kk][tx*2+1];
            a00 += x0*w0; a01 += x0*w1; a10 += x1*w0; a11 += x1*w1;
        }
        __syncthreads();
    }
    int r = row0 + ty*2, c = col0 + tx*2;
    C[r*DM + c]       = a00 + bias[c];
    C[r*DM + c + 1]   = a01 + bias[c+1];
    C[(r+1)*DM + c]   = a10 + bias[c];
    C[(r+1)*DM + c+1] = a11 + bias[c+1];
}
__global__ void k_gemm1(const float* __restrict__ W, const float* __restrict__ b) {
    gemm_body(g_X, W, b, g_P, IND);
}
__global__ void k_gemm2(const float* __restrict__ W, const float* __restrict__ b) {
    gemm_body(g_H, W, b, g_P2, DM);
}

// ---------------- Out = relu(A_norm @ P), A_norm built on the fly ----------------
__device__ __forceinline__ void amul_body(const float* __restrict__ P,
                                          float* __restrict__ O) {
    __shared__ float As[32][32];
    __shared__ float Ps[32][64];
    int blk = blockIdx.x;
    int b = blk / 16, rest = blk % 16;
    int n0 = (rest / 4)*32, c0 = (rest % 4)*64;
    int tid = threadIdx.x;
    int tx = tid & 63, ty = tid >> 6;
    float acc[8] = {0,0,0,0,0,0,0,0};
    const float* Ab = g_A   + b*NN*NN;
    const float* db = g_dis + b*NN;
    for (int k0 = 0; k0 < NN; k0 += 32) {
        #pragma unroll
        for (int l = 0; l < 4; ++l) {
            int e = tid + l*256; int i = e>>5, j = e&31;
            float v = Ab[(n0+i)*NN + k0 + j];
            if (n0+i == k0+j) v += 1.0f;               // A_hat = A + I
            As[i][j] = v * db[n0+i] * db[k0+j];
        }
        #pragma unroll
        for (int l = 0; l < 8; ++l) {
            int e = tid + l*256; int j = e>>6, c = e&63;
            Ps[j][c] = P[(b*NN + k0 + j)*DM + c0 + c];
        }
        __syncthreads();
        #pragma unroll
        for (int j = 0; j < 32; ++j) {
            float pv = Ps[j][tx];
            #pragma unroll
            for (int r = 0; r < 8; ++r) acc[r] += As[ty + 4*r][j] * pv;
        }
        __syncthreads();
    }
    #pragma unroll
    for (int r = 0; r < 8; ++r)
        O[(b*NN + n0 + ty + 4*r)*DM + c0 + tx] = fmaxf(acc[r], 0.0f);
}
__global__ void k_amul1() { amul_body(g_P,  g_H);  }
__global__ void k_amul2() { amul_body(g_P2, g_H2); }

// ---------------- final pool + sigmoid ----------------
__global__ void k_final(const float* __restrict__ Wc, const float* __restrict__ bc,
                        float* __restrict__ out) {
    __shared__ float red[DM];
    int b = blockIdx.x, t = threadIdx.x;
    float s = 0.f;
    #pragma unroll 4
    for (int nn = 0; nn < NN; ++nn) s += g_H2[(b*NN + nn)*DM + t];
    float g = s * (1.0f/128.0f);
    red[t] = g * Wc[t];
    __syncthreads();
    for (int st = 128; st > 0; st >>= 1) { if (t < st) red[t] += red[t+st]; __syncthreads(); }
    if (t == 0) {
        float v = red[0] + bc[0];
        out[b] = 1.0f / (1.0f + expf(-v));
    }
}

// ---------------- launch ----------------
extern "C" void kernel_launch(void* const* d_in, const int* in_sizes, int n_in,
                              void* d_out, int out_size) {
    const float* x   = (const float*)d_in[0];
    const float* gam = (const float*)d_in[1];
    const float* bet = (const float*)d_in[2];
    const float* W1  = (const float*)d_in[3];
    const float* b1  = (const float*)d_in[4];
    const float* W2  = (const float*)d_in[5];
    const float* b2  = (const float*)d_in[6];
    const float* Wc  = (const float*)d_in[7];
    const float* bc  = (const float*)d_in[8];
    float* out = (float*)d_out;

    k_musig   <<<BB*6, 128>>>(x);
    k_window  <<<BB*10, 256>>>(x);
    k_rowstats<<<3*BB*NN, 128>>>();
    k_ho      <<<BB*32, 128>>>();
    k_ln      <<<BB*NN, 128>>>(gam, bet);
    k_gemm1   <<<dim3(DM/32, BB*NN/32), dim3(16,16)>>>(W1, b1);
    k_amul1   <<<BB*16, 256>>>();
    k_gemm2   <<<dim3(DM/32, BB*NN/32), dim3(16,16)>>>(W2, b2);
    k_amul2   <<<BB*16, 256>>>();
    k_final   <<<BB, DM>>>(Wc, bc, out);
}

// round 6
// speedup vs baseline: 2.8949x; 2.8949x over previous
#include <cuda_runtime.h>
#include <math.h>

#define BB   16
#define TT   1024
#define NN   128
#define NW   498
#define DM   256
#define IND  384
#define NCH  8       // window chunks for main pass (64 windows each, last=50)
#define CHW  64
#define MCH  12      // window chunks for musig
#define MCW  42

// ---------------- scratch (static device globals; no allocation) ----------------
__device__ float g_mu  [BB*NW*NN];      // per (b,w,n) window mean
__device__ float g_rstd[BB*NW*NN];      // per (b,w,n) 1/std
__device__ float g_partA[NCH*BB*NN*NN]; // per-chunk partial corr sums
__device__ float g_mnC [BB*NN*NN];      // mean corr (upper tiles only)
__device__ float g_partB[3*NCH*BB*NN*NN]; // per-chunk partial moment sums
__device__ float g_cm  [3*BB*NN*NN];    // central moments d=2,4,8 (full, diag=0)
__device__ float g_rmean[3*BB*NN];
__device__ float g_rinv [3*BB*NN];
__device__ float g_A  [BB*NN*NN];       // averaged ho (diag=1)
__device__ float g_dis[BB*NN];          // rsqrt(rowsum(A)+1)
__device__ float g_X  [BB*NN*IND];      // layernormed features
__device__ float g_P  [BB*NN*DM];
__device__ float g_H  [BB*NN*DM];
__device__ float g_P2 [BB*NN*DM];
__device__ float g_H2 [BB*NN*DM];

__device__ const int c_ti[10] = {0,0,0,0,1,1,1,2,2,3};
__device__ const int c_tj[10] = {0,1,2,3,1,2,3,2,3,3};

#define LD4(p) (*reinterpret_cast<const float4*>(p))
#define ST4(p,v) (*reinterpret_cast<float4*>(p) = (v))

// ---------------- per-(b,w,n) mean / rstd, sliding sums, chunked ----------------
__global__ void k_musig(const float* __restrict__ x) {
    int b  = blockIdx.x / MCH;
    int ch = blockIdx.x % MCH;
    int n  = threadIdx.x;
    int w0 = ch * MCW, wend = min(w0 + MCW, NW);
    if (w0 >= NW) return;
    const float* xb = x + (size_t)b*TT*NN + n;
    float S = 0.f, Q = 0.f;
    int t0 = 2*w0;
    #pragma unroll
    for (int t = 0; t < 30; ++t) {
        float v = xb[(t0+t)*NN];
        S += v; Q += v*v;
    }
    for (int w = w0; w < wend; ++w) {
        if (w > w0) {
            int tp = 2*(w-1);
            float v0 = xb[tp*NN],      v1 = xb[(tp+1)*NN];
            float a0 = xb[(tp+30)*NN], a1 = xb[(tp+31)*NN];
            S += (a0 + a1) - (v0 + v1);
            Q += (a0*a0 + a1*a1) - (v0*v0 + v1*v1);
        }
        float mu  = S * (1.0f/30.0f);
        float var = (Q - S*S*(1.0f/30.0f)) * (1.0f/29.0f);
        float rs  = rsqrtf(fmaxf(var, 1e-8f));
        int idx = (b*NW + w)*NN + n;
        g_mu[idx]   = mu;
        g_rstd[idx] = rs;
    }
}

// ---------------- sliding-Gram helpers ----------------
__device__ __forceinline__ void gram_full(const float* __restrict__ xb,
                                          int n, int m0, int t0, float4& G) {
    G = make_float4(0.f, 0.f, 0.f, 0.f);
    const float* p = xb + t0*NN;
    #pragma unroll
    for (int t = 0; t < 30; ++t) {
        float  a = p[n];
        float4 v = LD4(p + m0);
        G.x += a*v.x; G.y += a*v.y; G.z += a*v.z; G.w += a*v.w;
        p += NN;
    }
}

__device__ __forceinline__ void gram_slide(const float* __restrict__ xb,
                                           int n, int m0, int w, float4& G) {
    const float* p = xb + (2*w)*NN;
    float a; float4 v;
    a = p[n - 2*NN]; v = LD4(p + m0 - 2*NN);
    G.x -= a*v.x; G.y -= a*v.y; G.z -= a*v.z; G.w -= a*v.w;
    a = p[n - NN];   v = LD4(p + m0 - NN);
    G.x -= a*v.x; G.y -= a*v.y; G.z -= a*v.z; G.w -= a*v.w;
    a = p[n + 28*NN]; v = LD4(p + m0 + 28*NN);
    G.x += a*v.x; G.y += a*v.y; G.z += a*v.z; G.w += a*v.w;
    a = p[n + 29*NN]; v = LD4(p + m0 + 29*NN);
    G.x += a*v.x; G.y += a*v.y; G.z += a*v.z; G.w += a*v.w;
}

__device__ __forceinline__ float4 corr4(const float4& G, float mun, float rn,
                                        const float4& mum, const float4& rm) {
    float s  = (1.0f/29.0f) * rn;
    float t2 = 30.0f * mun;
    float4 c;
    c.x = (G.x - t2*mum.x) * (s*rm.x);
    c.y = (G.y - t2*mum.y) * (s*rm.y);
    c.z = (G.z - t2*mum.z) * (s*rm.z);
    c.w = (G.w - t2*mum.w) * (s*rm.w);
    return c;
}

// ---------------- pass A (chunked): partial sums of corr over windows ----------------
__global__ void __launch_bounds__(256) k_winA(const float* __restrict__ x) {
    int blk  = blockIdx.x;
    int b    = blk / (10*NCH);
    int rest = blk % (10*NCH);
    int tile = rest / NCH;
    int ch   = rest % NCH;
    int tin = c_ti[tile], tjn = c_tj[tile];
    int tid = threadIdx.x;
    int n  = tin*32 + (tid >> 3);
    int m0 = tjn*32 + (tid & 7)*4;
    const float* xb = x + (size_t)b*TT*NN;
    int w0 = ch*CHW, wend = min(w0 + CHW, NW);

    float4 G;
    gram_full(xb, n, m0, 2*w0, G);
    float4 Cs = make_float4(0.f,0.f,0.f,0.f);
    const float* pmu = g_mu   + (b*NW + w0)*NN;
    const float* prs = g_rstd + (b*NW + w0)*NN;
    for (int w = w0; w < wend; ++w) {
        if (w > w0) gram_slide(xb, n, m0, w, G);
        float  mun = pmu[n], rn = prs[n];
        float4 mum = LD4(pmu + m0), rm = LD4(prs + m0);
        float4 c = corr4(G, mun, rn, mum, rm);
        Cs.x += c.x; Cs.y += c.y; Cs.z += c.z; Cs.w += c.w;
        pmu += NN; prs += NN;
    }
    ST4(&g_partA[((ch*BB + b)*NN + n)*NN + m0], Cs);
}

// ---------------- reduce pass A -> mean corr ----------------
__global__ void __launch_bounds__(256) k_redA() {
    int b    = blockIdx.x / 10;
    int tile = blockIdx.x % 10;
    int tin = c_ti[tile], tjn = c_tj[tile];
    int tid = threadIdx.x;
    int n  = tin*32 + (tid >> 3);
    int m0 = tjn*32 + (tid & 7)*4;
    float4 s = make_float4(0.f,0.f,0.f,0.f);
    #pragma unroll
    for (int ch = 0; ch < NCH; ++ch) {
        float4 p = LD4(&g_partA[((ch*BB + b)*NN + n)*NN + m0]);
        s.x += p.x; s.y += p.y; s.z += p.z; s.w += p.w;
    }
    const float inv = 1.0f/498.0f;
    s.x *= inv; s.y *= inv; s.z *= inv; s.w *= inv;
    ST4(&g_mnC[(b*NN + n)*NN + m0], s);
}

// ---------------- pass B (chunked): partial central-moment sums ----------------
__global__ void __launch_bounds__(256) k_winB(const float* __restrict__ x) {
    int blk  = blockIdx.x;
    int b    = blk / (10*NCH);
    int rest = blk % (10*NCH);
    int tile = rest / NCH;
    int ch   = rest % NCH;
    int tin = c_ti[tile], tjn = c_tj[tile];
    int tid = threadIdx.x;
    int n  = tin*32 + (tid >> 3);
    int m0 = tjn*32 + (tid & 7)*4;
    const float* xb = x + (size_t)b*TT*NN;
    int w0 = ch*CHW, wend = min(w0 + CHW, NW);

    float4 mn = LD4(&g_mnC[(b*NN + n)*NN + m0]);

    float4 G;
    gram_full(xb, n, m0, 2*w0, G);
    float4 p2 = make_float4(0.f,0.f,0.f,0.f);
    float4 p4 = make_float4(0.f,0.f,0.f,0.f);
    float4 p8 = make_float4(0.f,0.f,0.f,0.f);
    const float* pmu = g_mu   + (b*NW + w0)*NN;
    const float* prs = g_rstd + (b*NW + w0)*NN;
    for (int w = w0; w < wend; ++w) {
        if (w > w0) gram_slide(xb, n, m0, w, G);
        float  mun = pmu[n], rn = prs[n];
        float4 mum = LD4(pmu + m0), rm = LD4(prs + m0);
        float4 c = corr4(G, mun, rn, mum, rm);
        float dx = c.x - mn.x, dy = c.y - mn.y, dz = c.z - mn.z, dw = c.w - mn.w;
        float d2x = dx*dx, d2y = dy*dy, d2z = dz*dz, d2w = dw*dw;
        p2.x += d2x; p2.y += d2y; p2.z += d2z; p2.w += d2w;
        float d4x = d2x*d2x, d4y = d2y*d2y, d4z = d2z*d2z, d4w = d2w*d2w;
        p4.x += d4x; p4.y += d4y; p4.z += d4z; p4.w += d4w;
        p8.x += d4x*d4x; p8.y += d4y*d4y; p8.z += d4z*d4z; p8.w += d4w*d4w;
        pmu += NN; prs += NN;
    }
    const int D = BB*NN*NN;
    int base = ((ch*BB + b)*NN + n)*NN + m0;
    ST4(&g_partB[base], p2);
    ST4(&g_partB[NCH*D + base], p4);
    ST4(&g_partB[2*NCH*D + base], p8);
}

// ---------------- reduce pass B -> g_cm (scale, diag zero, mirror) ----------------
__global__ void __launch_bounds__(256) k_redB() {
    int b    = blockIdx.x / 10;
    int tile = blockIdx.x % 10;
    int tin = c_ti[tile], tjn = c_tj[tile];
    int tid = threadIdx.x;
    int n  = tin*32 + (tid >> 3);
    int m0 = tjn*32 + (tid & 7)*4;
    const int D = BB*NN*NN;
    const float inv = 1.0f/498.0f;
    #pragma unroll
    for (int d = 0; d < 3; ++d) {
        float4 s = make_float4(0.f,0.f,0.f,0.f);
        #pragma unroll
        for (int ch = 0; ch < NCH; ++ch) {
            float4 p = LD4(&g_partB[d*NCH*D + ((ch*BB + b)*NN + n)*NN + m0]);
            s.x += p.x; s.y += p.y; s.z += p.z; s.w += p.w;
        }
        float v[4] = {s.x*inv, s.y*inv, s.z*inv, s.w*inv};
        #pragma unroll
        for (int i = 0; i < 4; ++i) {
            int m = m0 + i;
            float vv = (n == m) ? 0.f : v[i];
            g_cm[d*D + (b*NN + n)*NN + m] = vv;
            if (tin != tjn) g_cm[d*D + (b*NN + m)*NN + n] = vv;
        }
    }
}

// ---------------- row stats of cm (for rowwise_corr) ----------------
__global__ void k_rowstats() {
    __shared__ float sm[NN];
    int row = blockIdx.x;          // (d*BB+b)*NN + n
    int t = threadIdx.x;
    float v = g_cm[row*NN + t];
    sm[t] = v; __syncthreads();
    for (int s = 64; s > 0; s >>= 1) { if (t < s) sm[t] += sm[t+s]; __syncthreads(); }
    float mean = sm[0] * (1.0f/128.0f);
    __syncthreads();
    float c = v - mean;
    sm[t] = c*c; __syncthreads();
    for (int s = 64; s > 0; s >>= 1) { if (t < s) sm[t] += sm[t+s]; __syncthreads(); }
    if (t == 0) {
        g_rmean[row] = mean;
        g_rinv[row]  = rsqrtf(fmaxf(sm[0], 1e-8f));
    }
}

// ---------------- ho = rowwise corr of each cm_d, averaged -> A ----------------
__global__ void __launch_bounds__(128) k_ho() {
    __shared__ float rowc[3][8][NN];
    __shared__ float rin[3][8];
    int b  = blockIdx.x / 16;
    int n0 = (blockIdx.x % 16) * 8;
    int t  = threadIdx.x;                     // = m
    #pragma unroll
    for (int d = 0; d < 3; ++d)
        #pragma unroll
        for (int r = 0; r < 8; ++r) {
            int row = (d*BB + b)*NN + n0 + r;
            rowc[d][r][t] = g_cm[row*NN + t] - g_rmean[row];
        }
    if (t < 24) { int d = t/8, r = t%8; rin[d][r] = g_rinv[(d*BB+b)*NN + n0 + r]; }
    __syncthreads();

    int m = t;
    float rm_m[3], ri_m[3];
    #pragma unroll
    for (int d = 0; d < 3; ++d) {
        rm_m[d] = g_rmean[(d*BB+b)*NN + m];
        ri_m[d] = g_rinv [(d*BB+b)*NN + m];
    }
    float acc[3][8] = {{0}};
    for (int f = 0; f < NN; ++f) {
        #pragma unroll
        for (int d = 0; d < 3; ++d) {
            float col = g_cm[((d*BB+b)*NN + f)*NN + m] - rm_m[d];  // cm symmetric
            #pragma unroll
            for (int r = 0; r < 8; ++r) acc[d][r] += rowc[d][r][f]*col;
        }
    }
    #pragma unroll
    for (int r = 0; r < 8; ++r) {
        float s = 0.f;
        #pragma unroll
        for (int d = 0; d < 3; ++d) {
            float corr = acc[d][r] * rin[d][r] * ri_m[d];
            if (n0 + r == m) corr = 1.0f;
            s += corr;
        }
        g_A[(b*NN + n0 + r)*NN + m] = s * (1.0f/3.0f);
    }
}

// ---------------- dis = rsqrt(rowsum(A)+1) ----------------
__global__ void k_dis() {
    __shared__ float red[NN];
    int b = blockIdx.x / NN, n = blockIdx.x % NN, t = threadIdx.x;
    red[t] = g_A[(b*NN + n)*NN + t];
    __syncthreads();
    for (int s = 64; s > 0; s >>= 1) { if (t < s) red[t] += red[t+s]; __syncthreads(); }
    if (t == 0) g_dis[b*NN + n] = rsqrtf(fmaxf(red[0] + 1.0f, 1e-8f));
}

// ---------------- X = layernorm(concat(cm2,cm4,cm8)) ----------------
__global__ void k_ln(const float* __restrict__ gam, const float* __restrict__ bet) {
    __shared__ float red[NN];
    int b = blockIdx.x / NN, n = blockIdx.x % NN, t = threadIdx.x;
    float v[3];
    #pragma unroll
    for (int d = 0; d < 3; ++d) v[d] = g_cm[((d*BB+b)*NN + n)*NN + t];
    red[t] = v[0] + v[1] + v[2]; __syncthreads();
    for (int s = 64; s > 0; s >>= 1) { if (t < s) red[t] += red[t+s]; __syncthreads(); }
    float mean = red[0] * (1.0f/384.0f);
    __syncthreads();
    float q = 0.f;
    #pragma unroll
    for (int d = 0; d < 3; ++d) { float c = v[d]-mean; q += c*c; }
    red[t] = q; __syncthreads();
    for (int s = 64; s > 0; s >>= 1) { if (t < s) red[t] += red[t+s]; __syncthreads(); }
    float rs = rsqrtf(red[0]*(1.0f/384.0f) + 1e-5f);
    #pragma unroll
    for (int d = 0; d < 3; ++d) {
        int f = d*NN + t;
        g_X[(b*NN + n)*IND + f] = (v[d]-mean)*rs*gam[f] + bet[f];
    }
}

// ---------------- generic small SGEMM: C = In@W + bias ----------------
__device__ __forceinline__ void gemm_body(const float* __restrict__ In,
                                          const float* __restrict__ W,
                                          const float* __restrict__ bias,
                                          float* __restrict__ C, int K) {
    __shared__ float As[32][33];
    __shared__ float Bs[32][33];
    int tx = threadIdx.x, ty = threadIdx.y;
    int tid = ty*16 + tx;
    int row0 = blockIdx.y*32, col0 = blockIdx.x*32;
    float a00=0.f, a01=0.f, a10=0.f, a11=0.f;
    for (int k0 = 0; k0 < K; k0 += 32) {
        #pragma unroll
        for (int l = 0; l < 4; ++l) {
            int e = tid + l*256; int i = e>>5, j = e&31;
            As[i][j] = In[(row0+i)*K + k0 + j];
            Bs[i][j] = W [(k0+i)*DM + col0 + j];
        }
        __syncthreads();
        #pragma unroll
        for (int kk = 0; kk < 32; ++kk) {
            float x0 = As[ty*2][kk],   x1 = As[ty*2+1][kk];
            float w0 = Bs[kk][tx*2],   w1 = Bs[kk][tx*2+1];
            a00 += x0*w0; a01 += x0*w1; a10 += x1*w0; a11 += x1*w1;
        }
        __syncthreads();
    }
    int r = row0 + ty*2, c = col0 + tx*2;
    C[r*DM + c]       = a00 + bias[c];
    C[r*DM + c + 1]   = a01 + bias[c+1];
    C[(r+1)*DM + c]   = a10 + bias[c];
    C[(r+1)*DM + c+1] = a11 + bias[c+1];
}
__global__ void k_gemm1(const float* __restrict__ W, const float* __restrict__ b) {
    gemm_body(g_X, W, b, g_P, IND);
}
__global__ void k_gemm2(const float* __restrict__ W, const float* __restrict__ b) {
    gemm_body(g_H, W, b, g_P2, DM);
}

// ---------------- Out = relu(A_norm @ P), A_norm built on the fly ----------------
__device__ __forceinline__ void amul_body(const float* __restrict__ P,
                                          float* __restrict__ O) {
    __shared__ float As[32][32];
    __shared__ float Ps[32][64];
    int blk = blockIdx.x;
    int b = blk / 16, rest = blk % 16;
    int n0 = (rest / 4)*32, c0 = (rest % 4)*64;
    int tid = threadIdx.x;
    int tx = tid & 63, ty = tid >> 6;
    float acc[8] = {0,0,0,0,0,0,0,0};
    const float* Ab = g_A   + b*NN*NN;
    const float* db = g_dis + b*NN;
    for (int k0 = 0; k0 < NN; k0 += 32) {
        #pragma unroll
        for (int l = 0; l < 4; ++l) {
            int e = tid + l*256; int i = e>>5, j = e&31;
            float v = Ab[(n0+i)*NN + k0 + j];
            if (n0+i == k0+j) v += 1.0f;               // A_hat = A + I
            As[i][j] = v * db[n0+i] * db[k0+j];
        }
        #pragma unroll
        for (int l = 0; l < 8; ++l) {
            int e = tid + l*256; int j = e>>6, c = e&63;
            Ps[j][c] = P[(b*NN + k0 + j)*DM + c0 + c];
        }
        __syncthreads();
        #pragma unroll
        for (int j = 0; j < 32; ++j) {
            float pv = Ps[j][tx];
            #pragma unroll
            for (int r = 0; r < 8; ++r) acc[r] += As[ty + 4*r][j] * pv;
        }
        __syncthreads();
    }
    #pragma unroll
    for (int r = 0; r < 8; ++r)
        O[(b*NN + n0 + ty + 4*r)*DM + c0 + tx] = fmaxf(acc[r], 0.0f);
}
__global__ void k_amul1() { amul_body(g_P,  g_H);  }
__global__ void k_amul2() { amul_body(g_P2, g_H2); }

// ---------------- final pool + sigmoid ----------------
__global__ void k_final(const float* __restrict__ Wc, const float* __restrict__ bc,
                        float* __restrict__ out) {
    __shared__ float red[DM];
    int b = blockIdx.x, t = threadIdx.x;
    float s = 0.f;
    #pragma unroll 4
    for (int nn = 0; nn < NN; ++nn) s += g_H2[(b*NN + nn)*DM + t];
    float g = s * (1.0f/128.0f);
    red[t] = g * Wc[t];
    __syncthreads();
    for (int st = 128; st > 0; st >>= 1) { if (t < st) red[t] += red[t+st]; __syncthreads(); }
    if (t == 0) {
        float v = red[0] + bc[0];
        out[b] = 1.0f / (1.0f + expf(-v));
    }
}

// ---------------- launch ----------------
extern "C" void kernel_launch(void* const* d_in, const int* in_sizes, int n_in,
                              void* d_out, int out_size) {
    const float* x   = (const float*)d_in[0];
    const float* gam = (const float*)d_in[1];
    const float* bet = (const float*)d_in[2];
    const float* W1  = (const float*)d_in[3];
    const float* b1  = (const float*)d_in[4];
    const float* W2  = (const float*)d_in[5];
    const float* b2  = (const float*)d_in[6];
    const float* Wc  = (const float*)d_in[7];
    const float* bc  = (const float*)d_in[8];
    float* out = (float*)d_out;

    k_musig   <<<BB*MCH, 128>>>(x);
    k_winA    <<<BB*10*NCH, 256>>>(x);
    k_redA    <<<BB*10, 256>>>();
    k_winB    <<<BB*10*NCH, 256>>>(x);
    k_redB    <<<BB*10, 256>>>();
    k_rowstats<<<3*BB*NN, 128>>>();
    k_ho      <<<BB*16, 128>>>();
    k_dis     <<<BB*NN, 128>>>();
    k_ln      <<<BB*NN, 128>>>(gam, bet);
    k_gemm1   <<<dim3(DM/32, BB*NN/32), dim3(16,16)>>>(W1, b1);
    k_amul1   <<<BB*16, 256>>>();
    k_gemm2   <<<dim3(DM/32, BB*NN/32), dim3(16,16)>>>(W2, b2);
    k_amul2   <<<BB*16, 256>>>();
    k_final   <<<BB, DM>>>(Wc, bc, out);
}

// round 7
// speedup vs baseline: 3.4452x; 1.1901x over previous
#include <cuda_runtime.h>
#include <math.h>

#define BB   16
#define TT   1024
#define NN   128
#define NW   498
#define DM   256
#define IND  384
#define NCH  8       // window chunks (64 windows each, last=50)
#define CHW  64
#define MCH  12      // window chunks for musig
#define MCW  42

// ---------------- scratch (static device globals; no allocation) ----------------
__device__ float g_mu  [BB*NW*NN];          // per (b,w,n) window mean
__device__ float g_rstd[BB*NW*NN];          // per (b,w,n) 1/std
__device__ float g_S   [8*NCH*BB*NN*NN];    // per-chunk partial power sums S1..S8
__device__ float g_cm  [3*BB*NN*NN];        // central moments d=2,4,8 (full, diag=0)
__device__ float g_rmean[3*BB*NN];
__device__ float g_rinv [3*BB*NN];
__device__ float g_A  [BB*NN*NN];           // averaged ho (diag=1)
__device__ float g_dis[BB*NN];              // rsqrt(rowsum(A)+1)
__device__ float g_X  [BB*NN*IND];          // layernormed features
__device__ float g_P  [BB*NN*DM];
__device__ float g_H  [BB*NN*DM];
__device__ float g_P2 [BB*NN*DM];
__device__ float g_H2 [BB*NN*DM];

__device__ const int c_ti[10] = {0,0,0,0,1,1,1,2,2,3};
__device__ const int c_tj[10] = {0,1,2,3,1,2,3,2,3,3};

#define LD4(p) (*reinterpret_cast<const float4*>(p))
#define LD2(p) (*reinterpret_cast<const float2*>(p))
#define ST4(p,v) (*reinterpret_cast<float4*>(p) = (v))

// ---------------- per-(b,w,n) mean / rstd, sliding sums, chunked ----------------
__global__ void k_musig(const float* __restrict__ x) {
    int b  = blockIdx.x / MCH;
    int ch = blockIdx.x % MCH;
    int n  = threadIdx.x;
    int w0 = ch * MCW, wend = min(w0 + MCW, NW);
    if (w0 >= NW) return;
    const float* xb = x + (size_t)b*TT*NN + n;
    float S = 0.f, Q = 0.f;
    int t0 = 2*w0;
    #pragma unroll
    for (int t = 0; t < 30; ++t) {
        float v = xb[(t0+t)*NN];
        S += v; Q += v*v;
    }
    for (int w = w0; w < wend; ++w) {
        if (w > w0) {
            int tp = 2*(w-1);
            float v0 = xb[tp*NN],      v1 = xb[(tp+1)*NN];
            float a0 = xb[(tp+30)*NN], a1 = xb[(tp+31)*NN];
            S += (a0 + a1) - (v0 + v1);
            Q += (a0*a0 + a1*a1) - (v0*v0 + v1*v1);
        }
        float mu  = S * (1.0f/30.0f);
        float var = (Q - S*S*(1.0f/30.0f)) * (1.0f/29.0f);
        float rs  = rsqrtf(fmaxf(var, 1e-8f));
        int idx = (b*NW + w)*NN + n;
        g_mu[idx]   = mu;
        g_rstd[idx] = rs;
    }
}

// ---------------- fused single pass: sliding Gram -> corr -> raw power sums ----------------
// Each thread: 2 consecutive n rows x 4 consecutive m cols. Accumulates
// S_p[pair] = sum_w corr^p for p=1..8 over its window chunk.
__global__ void __launch_bounds__(128, 4) k_winS(const float* __restrict__ x) {
    int blk  = blockIdx.x;
    int b    = blk / (10*NCH);
    int rest = blk % (10*NCH);
    int tile = rest / NCH;
    int ch   = rest % NCH;
    int tin = c_ti[tile], tjn = c_tj[tile];
    int tid = threadIdx.x;
    int n0 = tin*32 + (tid >> 3)*2;
    int m0 = tjn*32 + (tid & 7)*4;
    const float* xb = x + (size_t)b*TT*NN;
    int w0 = ch*CHW, wend = min(w0 + CHW, NW);

    // build Gram for the first window of the chunk
    float4 G0 = make_float4(0.f,0.f,0.f,0.f);
    float4 G1 = make_float4(0.f,0.f,0.f,0.f);
    {
        const float* p = xb + (2*w0)*NN;
        #pragma unroll
        for (int t = 0; t < 30; ++t) {
            float2 a = LD2(p + n0);
            float4 v = LD4(p + m0);
            G0.x += a.x*v.x; G0.y += a.x*v.y; G0.z += a.x*v.z; G0.w += a.x*v.w;
            G1.x += a.y*v.x; G1.y += a.y*v.y; G1.z += a.y*v.z; G1.w += a.y*v.w;
            p += NN;
        }
    }

    float S[8][8];
    #pragma unroll
    for (int p = 0; p < 8; ++p)
        #pragma unroll
        for (int k = 0; k < 8; ++k) S[p][k] = 0.f;

    const float* pmu = g_mu   + (b*NW + w0)*NN;
    const float* prs = g_rstd + (b*NW + w0)*NN;
    for (int w = w0; w < wend; ++w) {
        if (w > w0) {
            const float* p = xb + (2*w)*NN;
            float2 a; float4 v;
            a = LD2(p + n0 - 2*NN); v = LD4(p + m0 - 2*NN);
            G0.x -= a.x*v.x; G0.y -= a.x*v.y; G0.z -= a.x*v.z; G0.w -= a.x*v.w;
            G1.x -= a.y*v.x; G1.y -= a.y*v.y; G1.z -= a.y*v.z; G1.w -= a.y*v.w;
            a = LD2(p + n0 - NN);   v = LD4(p + m0 - NN);
            G0.x -= a.x*v.x; G0.y -= a.x*v.y; G0.z -= a.x*v.z; G0.w -= a.x*v.w;
            G1.x -= a.y*v.x; G1.y -= a.y*v.y; G1.z -= a.y*v.z; G1.w -= a.y*v.w;
            a = LD2(p + n0 + 28*NN); v = LD4(p + m0 + 28*NN);
            G0.x += a.x*v.x; G0.y += a.x*v.y; G0.z += a.x*v.z; G0.w += a.x*v.w;
            G1.x += a.y*v.x; G1.y += a.y*v.y; G1.z += a.y*v.z; G1.w += a.y*v.w;
            a = LD2(p + n0 + 29*NN); v = LD4(p + m0 + 29*NN);
            G0.x += a.x*v.x; G0.y += a.x*v.y; G0.z += a.x*v.z; G0.w += a.x*v.w;
            G1.x += a.y*v.x; G1.y += a.y*v.y; G1.z += a.y*v.z; G1.w += a.y*v.w;
        }
        float2 mun = LD2(pmu + n0);
        float2 rn  = LD2(prs + n0);
        float4 mum = LD4(pmu + m0);
        float4 rm  = LD4(prs + m0);
        #pragma unroll
        for (int i = 0; i < 2; ++i) {
            float mu_i = i ? mun.y : mun.x;
            float rs_i = i ? rn.y  : rn.x;
            float t2 = 30.0f * mu_i;
            float s  = (1.0f/29.0f) * rs_i;
            float4 G = i ? G1 : G0;
            float c[4];
            c[0] = (G.x - t2*mum.x) * (s*rm.x);
            c[1] = (G.y - t2*mum.y) * (s*rm.y);
            c[2] = (G.z - t2*mum.z) * (s*rm.z);
            c[3] = (G.w - t2*mum.w) * (s*rm.w);
            #pragma unroll
            for (int j = 0; j < 4; ++j) {
                int k = i*4 + j;
                float cv = c[j];
                float c2 = cv*cv;
                float c3 = c2*cv;
                float c4 = c2*c2;
                S[0][k] += cv;
                S[1][k] += c2;
                S[2][k] += c3;
                S[3][k] = fmaf(c2, c2, S[3][k]);
                S[4][k] = fmaf(c4, cv, S[4][k]);
                S[5][k] = fmaf(c4, c2, S[5][k]);
                S[6][k] = fmaf(c4, c3, S[6][k]);
                S[7][k] = fmaf(c4, c4, S[7][k]);
            }
        }
        pmu += NN; prs += NN;
    }

    const int D = NCH*BB*NN*NN;
    #pragma unroll
    for (int p = 0; p < 8; ++p) {
        #pragma unroll
        for (int i = 0; i < 2; ++i) {
            float4 v = make_float4(S[p][i*4], S[p][i*4+1], S[p][i*4+2], S[p][i*4+3]);
            ST4(&g_S[p*D + ((ch*BB + b)*NN + (n0+i))*NN + m0], v);
        }
    }
}

// ---------------- reduce: power sums -> central moments (binomial, double) ----------------
__global__ void __launch_bounds__(256) k_redS() {
    int b    = blockIdx.x / 10;
    int tile = blockIdx.x % 10;
    int tin = c_ti[tile], tjn = c_tj[tile];
    int tid = threadIdx.x;
    int n  = tin*32 + (tid >> 3);
    int m0 = tjn*32 + (tid & 7)*4;
    const int D = NCH*BB*NN*NN;
    float A[8][4];
    #pragma unroll
    for (int p = 0; p < 8; ++p) { A[p][0]=0.f; A[p][1]=0.f; A[p][2]=0.f; A[p][3]=0.f; }
    #pragma unroll
    for (int ch = 0; ch < NCH; ++ch) {
        #pragma unroll
        for (int p = 0; p < 8; ++p) {
            float4 v = LD4(&g_S[p*D + ((ch*BB + b)*NN + n)*NN + m0]);
            A[p][0]+=v.x; A[p][1]+=v.y; A[p][2]+=v.z; A[p][3]+=v.w;
        }
    }
    const int DC = BB*NN*NN;
    const double invN = 1.0/498.0;
    #pragma unroll
    for (int j = 0; j < 4; ++j) {
        int m = m0 + j;
        double a1=A[0][j]*invN, a2=A[1][j]*invN, a3=A[2][j]*invN, a4=A[3][j]*invN;
        double a5=A[4][j]*invN, a6=A[5][j]*invN, a7=A[6][j]*invN, a8=A[7][j]*invN;
        double mm = a1;
        double m_2 = mm*mm, m_3 = m_2*mm, m_4 = m_2*m_2;
        double m_5 = m_4*mm, m_6 = m_4*m_2, m_8 = m_4*m_4;
        double M2 = a2 - m_2;
        double M4 = a4 - 4.0*mm*a3 + 6.0*m_2*a2 - 3.0*m_4;
        double M8 = a8 - 8.0*mm*a7 + 28.0*m_2*a6 - 56.0*m_3*a5 + 70.0*m_4*a4
                    - 56.0*m_5*a3 + 28.0*m_6*a2 - 7.0*m_8;
        float v2 = (float)M2, v4 = (float)M4, v8 = (float)M8;
        if (n == m) { v2 = 0.f; v4 = 0.f; v8 = 0.f; }   // diag corr == 1 exactly
        int idx = (b*NN + n)*NN + m;
        g_cm[idx] = v2; g_cm[DC + idx] = v4; g_cm[2*DC + idx] = v8;
        if (tin != tjn) {
            int tdx = (b*NN + m)*NN + n;
            g_cm[tdx] = v2; g_cm[DC + tdx] = v4; g_cm[2*DC + tdx] = v8;
        }
    }
}

// ---------------- row stats of cm (for rowwise_corr) ----------------
__global__ void k_rowstats() {
    __shared__ float sm[NN];
    int row = blockIdx.x;          // (d*BB+b)*NN + n
    int t = threadIdx.x;
    float v = g_cm[row*NN + t];
    sm[t] = v; __syncthreads();
    for (int s = 64; s > 0; s >>= 1) { if (t < s) sm[t] += sm[t+s]; __syncthreads(); }
    float mean = sm[0] * (1.0f/128.0f);
    __syncthreads();
    float c = v - mean;
    sm[t] = c*c; __syncthreads();
    for (int s = 64; s > 0; s >>= 1) { if (t < s) sm[t] += sm[t+s]; __syncthreads(); }
    if (t == 0) {
        g_rmean[row] = mean;
        g_rinv[row]  = rsqrtf(fmaxf(sm[0], 1e-8f));
    }
}

// ---------------- ho = rowwise corr of each cm_d, averaged -> A ----------------
__global__ void __launch_bounds__(128) k_ho() {
    __shared__ float rowc[3][8][NN];
    __shared__ float rin[3][8];
    int b  = blockIdx.x / 16;
    int n0 = (blockIdx.x % 16) * 8;
    int t  = threadIdx.x;                     // = m
    #pragma unroll
    for (int d = 0; d < 3; ++d)
        #pragma unroll
        for (int r = 0; r < 8; ++r) {
            int row = (d*BB + b)*NN + n0 + r;
            rowc[d][r][t] = g_cm[row*NN + t] - g_rmean[row];
        }
    if (t < 24) { int d = t/8, r = t%8; rin[d][r] = g_rinv[(d*BB+b)*NN + n0 + r]; }
    __syncthreads();

    int m = t;
    float rm_m[3], ri_m[3];
    #pragma unroll
    for (int d = 0; d < 3; ++d) {
        rm_m[d] = g_rmean[(d*BB+b)*NN + m];
        ri_m[d] = g_rinv [(d*BB+b)*NN + m];
    }
    float acc[3][8] = {{0}};
    for (int f = 0; f < NN; ++f) {
        #pragma unroll
        for (int d = 0; d < 3; ++d) {
            float col = g_cm[((d*BB+b)*NN + f)*NN + m] - rm_m[d];  // cm symmetric
            #pragma unroll
            for (int r = 0; r < 8; ++r) acc[d][r] += rowc[d][r][f]*col;
        }
    }
    #pragma unroll
    for (int r = 0; r < 8; ++r) {
        float s = 0.f;
        #pragma unroll
        for (int d = 0; d < 3; ++d) {
            float corr = acc[d][r] * rin[d][r] * ri_m[d];
            if (n0 + r == m) corr = 1.0f;
            s += corr;
        }
        g_A[(b*NN + n0 + r)*NN + m] = s * (1.0f/3.0f);
    }
}

// ---------------- dis = rsqrt(rowsum(A)+1) ----------------
__global__ void k_dis() {
    __shared__ float red[NN];
    int b = blockIdx.x / NN, n = blockIdx.x % NN, t = threadIdx.x;
    red[t] = g_A[(b*NN + n)*NN + t];
    __syncthreads();
    for (int s = 64; s > 0; s >>= 1) { if (t < s) red[t] += red[t+s]; __syncthreads(); }
    if (t == 0) g_dis[b*NN + n] = rsqrtf(fmaxf(red[0] + 1.0f, 1e-8f));
}

// ---------------- X = layernorm(concat(cm2,cm4,cm8)) ----------------
__global__ void k_ln(const float* __restrict__ gam, const float* __restrict__ bet) {
    __shared__ float red[NN];
    int b = blockIdx.x / NN, n = blockIdx.x % NN, t = threadIdx.x;
    float v[3];
    #pragma unroll
    for (int d = 0; d < 3; ++d) v[d] = g_cm[((d*BB+b)*NN + n)*NN + t];
    red[t] = v[0] + v[1] + v[2]; __syncthreads();
    for (int s = 64; s > 0; s >>= 1) { if (t < s) red[t] += red[t+s]; __syncthreads(); }
    float mean = red[0] * (1.0f/384.0f);
    __syncthreads();
    float q = 0.f;
    #pragma unroll
    for (int d = 0; d < 3; ++d) { float c = v[d]-mean; q += c*c; }
    red[t] = q; __syncthreads();
    for (int s = 64; s > 0; s >>= 1) { if (t < s) red[t] += red[t+s]; __syncthreads(); }
    float rs = rsqrtf(red[0]*(1.0f/384.0f) + 1e-5f);
    #pragma unroll
    for (int d = 0; d < 3; ++d) {
        int f = d*NN + t;
        g_X[(b*NN + n)*IND + f] = (v[d]-mean)*rs*gam[f] + bet[f];
    }
}

// ---------------- generic small SGEMM: C = In@W + bias ----------------
__device__ __forceinline__ void gemm_body(const float* __restrict__ In,
                                          const float* __restrict__ W,
                                          const float* __restrict__ bias,
                                          float* __restrict__ C, int K) {
    __shared__ float As[32][33];
    __shared__ float Bs[32][33];
    int tx = threadIdx.x, ty = threadIdx.y;
    int tid = ty*16 + tx;
    int row0 = blockIdx.y*32, col0 = blockIdx.x*32;
    float a00=0.f, a01=0.f, a10=0.f, a11=0.f;
    for (int k0 = 0; k0 < K; k0 += 32) {
        #pragma unroll
        for (int l = 0; l < 4; ++l) {
            int e = tid + l*256; int i = e>>5, j = e&31;
            As[i][j] = In[(row0+i)*K + k0 + j];
            Bs[i][j] = W [(k0+i)*DM + col0 + j];
        }
        __syncthreads();
        #pragma unroll
        for (int kk = 0; kk < 32; ++kk) {
            float x0 = As[ty*2][kk],   x1 = As[ty*2+1][kk];
            float w0 = Bs[kk][tx*2],   w1 = Bs[kk][tx*2+1];
            a00 += x0*w0; a01 += x0*w1; a10 += x1*w0; a11 += x1*w1;
        }
        __syncthreads();
    }
    int r = row0 + ty*2, c = col0 + tx*2;
    C[r*DM + c]       = a00 + bias[c];
    C[r*DM + c + 1]   = a01 + bias[c+1];
    C[(r+1)*DM + c]   = a10 + bias[c];
    C[(r+1)*DM + c+1] = a11 + bias[c+1];
}
__global__ void k_gemm1(const float* __restrict__ W, const float* __restrict__ b) {
    gemm_body(g_X, W, b, g_P, IND);
}
__global__ void k_gemm2(const float* __restrict__ W, const float* __restrict__ b) {
    gemm_body(g_H, W, b, g_P2, DM);
}

// ---------------- Out = relu(A_norm @ P), A_norm built on the fly ----------------
__device__ __forceinline__ void amul_body(const float* __restrict__ P,
                                          float* __restrict__ O) {
    __shared__ float As[32][32];
    __shared__ float Ps[32][64];
    int blk = blockIdx.x;
    int b = blk / 16, rest = blk % 16;
    int n0 = (rest / 4)*32, c0 = (rest % 4)*64;
    int tid = threadIdx.x;
    int tx = tid & 63, ty = tid >> 6;
    float acc[8] = {0,0,0,0,0,0,0,0};
    const float* Ab = g_A   + b*NN*NN;
    const float* db = g_dis + b*NN;
    for (int k0 = 0; k0 < NN; k0 += 32) {
        #pragma unroll
        for (int l = 0; l < 4; ++l) {
            int e = tid + l*256; int i = e>>5, j = e&31;
            float v = Ab[(n0+i)*NN + k0 + j];
            if (n0+i == k0+j) v += 1.0f;               // A_hat = A + I
            As[i][j] = v * db[n0+i] * db[k0+j];
        }
        #pragma unroll
        for (int l = 0; l < 8; ++l) {
            int e = tid + l*256; int j = e>>6, c = e&63;
            Ps[j][c] = P[(b*NN + k0 + j)*DM + c0 + c];
        }
        __syncthreads();
        #pragma unroll
        for (int j = 0; j < 32; ++j) {
            float pv = Ps[j][tx];
            #pragma unroll
            for (int r = 0; r < 8; ++r) acc[r] += As[ty + 4*r][j] * pv;
        }
        __syncthreads();
    }
    #pragma unroll
    for (int r = 0; r < 8; ++r)
        O[(b*NN + n0 + ty + 4*r)*DM + c0 + tx] = fmaxf(acc[r], 0.0f);
}
__global__ void k_amul1() { amul_body(g_P,  g_H);  }
__global__ void k_amul2() { amul_body(g_P2, g_H2); }

// ---------------- final pool + sigmoid ----------------
__global__ void k_final(const float* __restrict__ Wc, const float* __restrict__ bc,
                        float* __restrict__ out) {
    __shared__ float red[DM];
    int b = blockIdx.x, t = threadIdx.x;
    float s = 0.f;
    #pragma unroll 4
    for (int nn = 0; nn < NN; ++nn) s += g_H2[(b*NN + nn)*DM + t];
    float g = s * (1.0f/128.0f);
    red[t] = g * Wc[t];
    __syncthreads();
    for (int st = 128; st > 0; st >>= 1) { if (t < st) red[t] += red[t+st]; __syncthreads(); }
    if (t == 0) {
        float v = red[0] + bc[0];
        out[b] = 1.0f / (1.0f + expf(-v));
    }
}

// ---------------- launch ----------------
extern "C" void kernel_launch(void* const* d_in, const int* in_sizes, int n_in,
                              void* d_out, int out_size) {
    const float* x   = (const float*)d_in[0];
    const float* gam = (const float*)d_in[1];
    const float* bet = (const float*)d_in[2];
    const float* W1  = (const float*)d_in[3];
    const float* b1  = (const float*)d_in[4];
    const float* W2  = (const float*)d_in[5];
    const float* b2  = (const float*)d_in[6];
    const float* Wc  = (const float*)d_in[7];
    const float* bc  = (const float*)d_in[8];
    float* out = (float*)d_out;

    k_musig   <<<BB*MCH, 128>>>(x);
    k_winS    <<<BB*10*NCH, 128>>>(x);
    k_redS    <<<BB*10, 256>>>();
    k_rowstats<<<3*BB*NN, 128>>>();
    k_ho      <<<BB*16, 128>>>();
    k_dis     <<<BB*NN, 128>>>();
    k_ln      <<<BB*NN, 128>>>(gam, bet);
    k_gemm1   <<<dim3(DM/32, BB*NN/32), dim3(16,16)>>>(W1, b1);
    k_amul1   <<<BB*16, 256>>>();
    k_gemm2   <<<dim3(DM/32, BB*NN/32), dim3(16,16)>>>(W2, b2);
    k_amul2   <<<BB*16, 256>>>();
    k_final   <<<BB, DM>>>(Wc, bc, out);
}